// round 14
// baseline (speedup 1.0000x reference)
#include <cuda_runtime.h>
#include <cstdint>

#define NBLOCKS  296
#define NTHREADS 288              // 8 consumer warps + 1 producer warp
#define NCONS    256
#define CWARPS   8
#define PROD_W   8
#define TILE     512              // 2 rows per consumer thread
#define STAGES   3
#define EPS      0.0001f

__device__ double       g_partials[NBLOCKS];
__device__ unsigned int g_counter = 0;

// z = clamp((x-u)/s, -3, 3): exact simplification of
// sqrt2*erfinv(2*clip(ndtr(t),eps,1-eps)-1) clipped to [-3,3]
// (Phi^-1(eps) = -3.719 < -3 so the eps clip never binds in [-3,3]).
// nll = 0.5*t^2 + param (s = exp(param)); 1/s = exp(-param); EPS floor
// binds only at param <= -9.21, far outside data range; z-clamp bounds it anyway.
__device__ __forceinline__ float row_loss(
    float ra, float rb,
    float pu1, float ps1, float pu2, float ps2, float pu3, float ps3,
    float r12, float r13, float r23,
    float revert, float Rtop, float Top, float Close)
{
    float u1 = __expf(pu1), rs1 = __expf(-ps1);
    float u2 = __expf(pu2), rs2 = __expf(-ps2);
    float u3 = __expf(pu3), rs3 = __expf(-ps3);

    float t1 = (Rtop  - u1) * rs1;
    float t2 = (Top   - u2) * rs2;
    float t3 = (Close - u3) * rs3;
    float z1 = fminf(fmaxf(t1, -3.0f), 3.0f);
    float z2 = fminf(fmaxf(t2, -3.0f), 3.0f);
    float z3 = fminf(fmaxf(t3, -3.0f), 3.0f);

    float nll_sum = 0.5f * (t1 * t1 + t2 * t2 + t3 * t3) + (ps1 + ps2 + ps3);

    float detR = 1.0f + 2.0f * r12 * r13 * r23
               - r12 * r12 - r13 * r13 - r23 * r23;
    float inv_det = 1.0f / detR;
    float i00 = (1.0f - r23 * r23) * inv_det;
    float i01 = (r13 * r23 - r12) * inv_det;
    float i02 = (r12 * r23 - r13) * inv_det;
    float i11 = (1.0f - r13 * r13) * inv_det;
    float i12 = (r12 * r13 - r23) * inv_det;
    float i22 = (1.0f - r12 * r12) * inv_det;

    float exp_term = 0.5f * ((i00 - 1.0f) * z1 * z1
                           + (i11 - 1.0f) * z2 * z2
                           + (i22 - 1.0f) * z3 * z3)
                   + (i01 * z1 * z2 + i02 * z1 * z3 + i12 * z2 * z3);

    float c_gauss = 0.5f * __logf(fmaxf(detR, EPS)) + exp_term;
    float copula  = revert * (c_gauss + nll_sum);

    float m   = fmaxf(ra, rb);
    float lse = m + __logf(1.0f + __expf(-fabsf(ra - rb)));
    float sel = (revert != 0.0f) ? rb : ra;
    return (lse - sel) + copula;
}

__device__ __forceinline__ uint32_t smem_u32(const void* p) {
    return (uint32_t)__cvta_generic_to_shared(p);
}
__device__ __forceinline__ void mbar_init(uint32_t mbar, uint32_t cnt) {
    asm volatile("mbarrier.init.shared.b64 [%0], %1;" :: "r"(mbar), "r"(cnt) : "memory");
}
__device__ __forceinline__ void mbar_expect_tx(uint32_t mbar, uint32_t bytes) {
    asm volatile("mbarrier.arrive.expect_tx.shared.b64 _, [%0], %1;"
                 :: "r"(mbar), "r"(bytes) : "memory");
}
__device__ __forceinline__ void mbar_arrive(uint32_t mbar) {
    asm volatile("mbarrier.arrive.shared.b64 _, [%0];" :: "r"(mbar) : "memory");
}
__device__ __forceinline__ void bulk_g2s(uint32_t dst, const void* src,
                                         uint32_t bytes, uint32_t mbar) {
    asm volatile(
        "cp.async.bulk.shared::cta.global.mbarrier::complete_tx::bytes "
        "[%0], [%1], %2, [%3];"
        :: "r"(dst), "l"(src), "r"(bytes), "r"(mbar) : "memory");
}
__device__ __forceinline__ void mbar_wait(uint32_t mbar, uint32_t parity) {
    uint32_t done;
    asm volatile(
        "{\n\t.reg .pred p;\n\t"
        "mbarrier.try_wait.parity.acquire.cta.shared::cta.b64 p, [%1], %2;\n\t"
        "selp.b32 %0, 1, 0, p;\n\t}"
        : "=r"(done) : "r"(mbar), "r"(parity) : "memory");
    if (!done) {
        asm volatile(
            "{\n\t.reg .pred P1;\n\t"
            "WL_%=:\n\t"
            "mbarrier.try_wait.parity.acquire.cta.shared::cta.b64 P1, [%0], %1, 0x989680;\n\t"
            "@P1 bra.uni WD_%=;\n\t"
            "bra.uni WL_%=;\n\t"
            "WD_%=:\n\t}"
            :: "r"(mbar), "r"(parity) : "memory");
    }
}

__global__ __launch_bounds__(NTHREADS, 2)
void gausscop_ws(const float* __restrict__ pred_r,
                 const float* __restrict__ pred_params,
                 const float* __restrict__ pred_corr,
                 const float* __restrict__ y_true,
                 float* __restrict__ out,
                 int n)
{
    __shared__ alignas(128) float s_r[STAGES][TILE * 2];  //  4 KB/stage
    __shared__ alignas(128) float s_p[STAGES][TILE * 6];  // 12 KB/stage
    __shared__ alignas(128) float s_c[STAGES][TILE * 3];  //  6 KB/stage
    __shared__ alignas(128) float s_y[STAGES][TILE * 4];  //  8 KB/stage
    __shared__ alignas(8)  uint64_t full_bar[STAGES];
    __shared__ alignas(8)  uint64_t empty_bar[STAGES];

    const int tid  = threadIdx.x;
    const int lane = tid & 31;
    const int wid  = tid >> 5;
    const uint32_t fb0 = smem_u32(&full_bar[0]);
    const uint32_t eb0 = smem_u32(&empty_bar[0]);

    if (tid == 0) {
        #pragma unroll
        for (int s = 0; s < STAGES; s++) {
            mbar_init(fb0 + 8u * s, 1);        // tx-based (producer expect_tx)
            mbar_init(eb0 + 8u * s, CWARPS);   // one arrive per consumer warp
        }
    }
    __syncthreads();

    const int ntiles = n / TILE;
    int nlocal = 0;
    if ((int)blockIdx.x < ntiles)
        nlocal = (ntiles - blockIdx.x + NBLOCKS - 1) / NBLOCKS;

    const uint32_t TILE_BYTES = TILE * 60u;

    float acc = 0.0f;

    if (wid == PROD_W) {
        // ======= producer warp: TMA issue only =======
        int slot = 0, phase = 1;   // flipped phase: first STAGES empty-waits pass
        for (int j = 0; j < nlocal; j++) {
            mbar_wait(eb0 + 8u * slot, (uint32_t)phase);
            if (lane == 0) {
                long base = ((long)blockIdx.x + (long)j * NBLOCKS) * TILE;
                uint32_t mb = fb0 + 8u * slot;
                mbar_expect_tx(mb, TILE_BYTES);
                bulk_g2s(smem_u32(s_r[slot]), pred_r      + 2 * base, TILE * 8,  mb);
                bulk_g2s(smem_u32(s_p[slot]), pred_params + 6 * base, TILE * 24, mb);
                bulk_g2s(smem_u32(s_c[slot]), pred_corr   + 3 * base, TILE * 12, mb);
                bulk_g2s(smem_u32(s_y[slot]), y_true      + 4 * base, TILE * 16, mb);
            }
            if (++slot == STAGES) { slot = 0; phase ^= 1; }
        }
    } else {
        // ======= consumer warps: 2 rows per thread per tile =======
        int slot = 0, phase = 0;
        for (int j = 0; j < nlocal; j++) {
            mbar_wait(fb0 + 8u * slot, (uint32_t)phase);

            const int rA = tid;          // 0..255
            const int rB = tid + NCONS;  // 256..511

            // drain both rows into registers (short slot dwell)
            float2 rrA = *(const float2*)(s_r[slot] + 2 * rA);
            float2 rrB = *(const float2*)(s_r[slot] + 2 * rB);
            const float2* ppA = (const float2*)(s_p[slot] + 6 * rA);
            float2 pA01 = ppA[0], pA23 = ppA[1], pA45 = ppA[2];
            const float2* ppB = (const float2*)(s_p[slot] + 6 * rB);
            float2 pB01 = ppB[0], pB23 = ppB[1], pB45 = ppB[2];
            const float* ccA = s_c[slot] + 3 * rA;
            float cA0 = ccA[0], cA1 = ccA[1], cA2 = ccA[2];
            const float* ccB = s_c[slot] + 3 * rB;
            float cB0 = ccB[0], cB1 = ccB[1], cB2 = ccB[2];
            float4 yA = *(const float4*)(s_y[slot] + 4 * rA);
            float4 yB = *(const float4*)(s_y[slot] + 4 * rB);

            __syncwarp();
            if (lane == 0) mbar_arrive(eb0 + 8u * slot);

            // compute overlaps the producer's refill of this slot
            acc += row_loss(rrA.x, rrA.y,
                            pA01.x, pA01.y, pA23.x, pA23.y, pA45.x, pA45.y,
                            cA0, cA1, cA2,
                            yA.x, yA.y, yA.z, yA.w);
            acc += row_loss(rrB.x, rrB.y,
                            pB01.x, pB01.y, pB23.x, pB23.y, pB45.x, pB45.y,
                            cB0, cB1, cB2,
                            yB.x, yB.y, yB.z, yB.w);

            if (++slot == STAGES) { slot = 0; phase ^= 1; }
        }

        // tail rows (n % TILE): direct loads, block 0 consumers only
        if (blockIdx.x == 0) {
            for (int i = ntiles * TILE + tid; i < n; i += NCONS) {
                long li = i;
                float2 rr  = *(const float2*)(pred_r      + 2 * li);
                float2 p01 = *(const float2*)(pred_params + 6 * li);
                float2 p23 = *(const float2*)(pred_params + 6 * li + 2);
                float2 p45 = *(const float2*)(pred_params + 6 * li + 4);
                const float* pc = pred_corr + 3 * li;
                float4 y   = *(const float4*)(y_true + 4 * li);
                acc += row_loss(rr.x, rr.y,
                                p01.x, p01.y, p23.x, p23.y, p45.x, p45.y,
                                pc[0], pc[1], pc[2],
                                y.x, y.y, y.z, y.w);
            }
        }
    }

    // ---- intra-block reduce (9 warps; producer contributes 0) ----
    #pragma unroll
    for (int o = 16; o; o >>= 1)
        acc += __shfl_xor_sync(0xFFFFFFFFu, acc, o);

    __shared__ float warpsums[NTHREADS / 32];
    __shared__ bool  amLast;
    if (lane == 0) warpsums[wid] = acc;
    __syncthreads();

    if (tid == 0) {
        double bs = 0.0;
        #pragma unroll
        for (int w = 0; w < NTHREADS / 32; w++) bs += (double)warpsums[w];
        g_partials[blockIdx.x] = bs;
        __threadfence();
        unsigned int tk = atomicAdd(&g_counter, 1u);
        amLast = (tk == gridDim.x - 1);
    }
    __syncthreads();

    // ---- last block: deterministic final reduction ----
    if (amLast) {
        __shared__ double sh[NTHREADS];
        double s = 0.0;
        volatile double* gpp = g_partials;
        for (int k = tid; k < NBLOCKS; k += NTHREADS) s += gpp[k];
        sh[tid] = s;
        __syncthreads();
        // fold the 32 extra lanes (256..287) into 0..31, then tree over 256
        if (tid < NTHREADS - 256) sh[tid] += sh[256 + tid];
        __syncthreads();
        for (int st = 128; st > 0; st >>= 1) {
            if (tid < st) sh[tid] += sh[tid + st];
            __syncthreads();
        }
        if (tid == 0) {
            out[0] = (float)(sh[0] / (double)n);
            g_counter = 0;   // reset for next graph replay
        }
    }
}

extern "C" void kernel_launch(void* const* d_in, const int* in_sizes, int n_in,
                              void* d_out, int out_size)
{
    const float* pred_r      = (const float*)d_in[0];
    const float* pred_params = (const float*)d_in[1];
    const float* pred_corr   = (const float*)d_in[2];
    const float* y_true      = (const float*)d_in[3];
    int n = in_sizes[0] / 2;   // pred_r is (B, 2)

    gausscop_ws<<<NBLOCKS, NTHREADS>>>(pred_r, pred_params, pred_corr,
                                       y_true, (float*)d_out, n);
}

// round 15
// speedup vs baseline: 1.0097x; 1.0097x over previous
#include <cuda_runtime.h>
#include <cstdint>

#define NBLOCKS  296
#define NTHREADS 288              // 8 consumer warps + 1 producer warp
#define NCONS    256
#define CWARPS   8
#define PROD_W   8
#define TILE     256
#define STAGES   4
#define LAG      2                // cp.async groups allowed in flight
#define EPS      0.0001f

__device__ double       g_partials[NBLOCKS];
__device__ unsigned int g_counter = 0;

// z = clamp((x-u)/s, -3, 3): exact simplification of
// sqrt2*erfinv(2*clip(ndtr(t),eps,1-eps)-1) clipped to [-3,3]
// (Phi^-1(eps) = -3.719 < -3 so the eps clip never binds in [-3,3]).
// nll = 0.5*t^2 + param (s = exp(param)); 1/s = exp(-param); EPS floor
// binds only at param <= -9.21, far outside data range; z-clamp bounds it anyway.
__device__ __forceinline__ float row_loss(
    float ra, float rb,
    float pu1, float ps1, float pu2, float ps2, float pu3, float ps3,
    float r12, float r13, float r23,
    float revert, float Rtop, float Top, float Close)
{
    float u1 = __expf(pu1), rs1 = __expf(-ps1);
    float u2 = __expf(pu2), rs2 = __expf(-ps2);
    float u3 = __expf(pu3), rs3 = __expf(-ps3);

    float t1 = (Rtop  - u1) * rs1;
    float t2 = (Top   - u2) * rs2;
    float t3 = (Close - u3) * rs3;
    float z1 = fminf(fmaxf(t1, -3.0f), 3.0f);
    float z2 = fminf(fmaxf(t2, -3.0f), 3.0f);
    float z3 = fminf(fmaxf(t3, -3.0f), 3.0f);

    float nll_sum = 0.5f * (t1 * t1 + t2 * t2 + t3 * t3) + (ps1 + ps2 + ps3);

    float detR = 1.0f + 2.0f * r12 * r13 * r23
               - r12 * r12 - r13 * r13 - r23 * r23;
    float inv_det = 1.0f / detR;
    float i00 = (1.0f - r23 * r23) * inv_det;
    float i01 = (r13 * r23 - r12) * inv_det;
    float i02 = (r12 * r23 - r13) * inv_det;
    float i11 = (1.0f - r13 * r13) * inv_det;
    float i12 = (r12 * r13 - r23) * inv_det;
    float i22 = (1.0f - r12 * r12) * inv_det;

    float exp_term = 0.5f * ((i00 - 1.0f) * z1 * z1
                           + (i11 - 1.0f) * z2 * z2
                           + (i22 - 1.0f) * z3 * z3)
                   + (i01 * z1 * z2 + i02 * z1 * z3 + i12 * z2 * z3);

    float c_gauss = 0.5f * __logf(fmaxf(detR, EPS)) + exp_term;
    float copula  = revert * (c_gauss + nll_sum);

    float m   = fmaxf(ra, rb);
    float lse = m + __logf(1.0f + __expf(-fabsf(ra - rb)));
    float sel = (revert != 0.0f) ? rb : ra;
    return (lse - sel) + copula;
}

__device__ __forceinline__ uint32_t smem_u32(const void* p) {
    return (uint32_t)__cvta_generic_to_shared(p);
}
__device__ __forceinline__ void mbar_init(uint32_t mbar, uint32_t cnt) {
    asm volatile("mbarrier.init.shared.b64 [%0], %1;" :: "r"(mbar), "r"(cnt) : "memory");
}
__device__ __forceinline__ void mbar_expect_tx(uint32_t mbar, uint32_t bytes) {
    asm volatile("mbarrier.arrive.expect_tx.shared.b64 _, [%0], %1;"
                 :: "r"(mbar), "r"(bytes) : "memory");
}
__device__ __forceinline__ void mbar_arrive(uint32_t mbar) {
    asm volatile("mbarrier.arrive.shared.b64 _, [%0];" :: "r"(mbar) : "memory");
}
__device__ __forceinline__ void bulk_g2s(uint32_t dst, const void* src,
                                         uint32_t bytes, uint32_t mbar) {
    asm volatile(
        "cp.async.bulk.shared::cta.global.mbarrier::complete_tx::bytes "
        "[%0], [%1], %2, [%3];"
        :: "r"(dst), "l"(src), "r"(bytes), "r"(mbar) : "memory");
}
__device__ __forceinline__ void cp_async16(uint32_t dst, const void* src) {
    asm volatile("cp.async.cg.shared.global [%0], [%1], 16;"
                 :: "r"(dst), "l"(src) : "memory");
}
__device__ __forceinline__ void cp_commit() {
    asm volatile("cp.async.commit_group;" ::: "memory");
}
template <int N>
__device__ __forceinline__ void cp_wait() {
    asm volatile("cp.async.wait_group %0;" :: "n"(N) : "memory");
}
__device__ __forceinline__ void mbar_wait(uint32_t mbar, uint32_t parity) {
    uint32_t done;
    asm volatile(
        "{\n\t.reg .pred p;\n\t"
        "mbarrier.try_wait.parity.acquire.cta.shared::cta.b64 p, [%1], %2;\n\t"
        "selp.b32 %0, 1, 0, p;\n\t}"
        : "=r"(done) : "r"(mbar), "r"(parity) : "memory");
    if (!done) {
        asm volatile(
            "{\n\t.reg .pred P1;\n\t"
            "WL_%=:\n\t"
            "mbarrier.try_wait.parity.acquire.cta.shared::cta.b64 P1, [%0], %1, 0x989680;\n\t"
            "@P1 bra.uni WD_%=;\n\t"
            "bra.uni WL_%=;\n\t"
            "WD_%=:\n\t}"
            :: "r"(mbar), "r"(parity) : "memory");
    }
}

__global__ __launch_bounds__(NTHREADS, 2)
void gausscop_dual(const float* __restrict__ pred_r,
                   const float* __restrict__ pred_params,
                   const float* __restrict__ pred_corr,
                   const float* __restrict__ y_true,
                   float* __restrict__ out,
                   int n)
{
    __shared__ alignas(128) float s_r[STAGES][TILE * 2];  // via cp.async
    __shared__ alignas(128) float s_p[STAGES][TILE * 6];  // via TMA
    __shared__ alignas(128) float s_c[STAGES][TILE * 3];  // via TMA
    __shared__ alignas(128) float s_y[STAGES][TILE * 4];  // via cp.async
    __shared__ alignas(8)  uint64_t full_bar[STAGES];
    __shared__ alignas(8)  uint64_t empty_bar[STAGES];

    const int tid  = threadIdx.x;
    const int lane = tid & 31;
    const int wid  = tid >> 5;
    const uint32_t fb0 = smem_u32(&full_bar[0]);
    const uint32_t eb0 = smem_u32(&empty_bar[0]);

    if (tid == 0) {
        #pragma unroll
        for (int s = 0; s < STAGES; s++) {
            // full: 2 arrives (expect_tx at issue + post-wait_group) + TMA tx
            mbar_init(fb0 + 8u * s, 2);
            mbar_init(eb0 + 8u * s, CWARPS);   // one arrive per consumer warp
        }
    }
    __syncthreads();

    const int ntiles = n / TILE;
    int nlocal = 0;
    if ((int)blockIdx.x < ntiles)
        nlocal = (ntiles - blockIdx.x + NBLOCKS - 1) / NBLOCKS;

    const uint32_t TMA_BYTES = TILE * 36u;    // params 24B + corr 12B per row

    float acc = 0.0f;

    if (wid == PROD_W) {
        // ======= producer warp: TMA (params,corr) + cp.async (pred_r,y_true) =======
        int slot = 0, phase = 1;   // flipped phase: first STAGES empty-waits pass
        for (int j = 0; j < nlocal; j++) {
            mbar_wait(eb0 + 8u * slot, (uint32_t)phase);
            long base = ((long)blockIdx.x + (long)j * NBLOCKS) * TILE;

            if (lane == 0) {
                uint32_t mb = fb0 + 8u * slot;
                mbar_expect_tx(mb, TMA_BYTES);                    // arrive 1 of 2
                bulk_g2s(smem_u32(s_p[slot]), pred_params + 6 * base, TILE * 24, mb);
                bulk_g2s(smem_u32(s_c[slot]), pred_corr   + 3 * base, TILE * 12, mb);
            }

            // cp.async leg: pred_r 2KB (128 x 16B) + y_true 4KB (256 x 16B)
            {
                const char* gr = (const char*)(pred_r + 2 * base);
                uint32_t sr = smem_u32(s_r[slot]);
                #pragma unroll
                for (int k = 0; k < 4; k++) {
                    int off = (lane + 32 * k) * 16;
                    cp_async16(sr + off, gr + off);
                }
                const char* gy = (const char*)(y_true + 4 * base);
                uint32_t sy = smem_u32(s_y[slot]);
                #pragma unroll
                for (int k = 0; k < 8; k++) {
                    int off = (lane + 32 * k) * 16;
                    cp_async16(sy + off, gy + off);
                }
                cp_commit();
            }

            // lagged completion: when group j-LAG has landed, give its slot
            // the second arrive (publishes cp.async data to consumers)
            if (j >= LAG) {
                cp_wait<LAG>();
                if (lane == 0) mbar_arrive(fb0 + 8u * ((j - LAG) % STAGES));
            }

            if (++slot == STAGES) { slot = 0; phase ^= 1; }
        }
        // drain remaining groups
        if (nlocal >= 2) {
            cp_wait<1>();
            if (lane == 0) mbar_arrive(fb0 + 8u * ((nlocal - 2) % STAGES));
        }
        if (nlocal >= 1) {
            cp_wait<0>();
            if (lane == 0) mbar_arrive(fb0 + 8u * ((nlocal - 1) % STAGES));
        }
    } else {
        // ======= consumer warps =======
        int slot = 0, phase = 0;
        for (int j = 0; j < nlocal; j++) {
            mbar_wait(fb0 + 8u * slot, (uint32_t)phase);

            // drain this thread's row into registers (short slot dwell)
            float2 rr = *(const float2*)(s_r[slot] + 2 * tid);
            const float2* pp2 = (const float2*)(s_p[slot] + 6 * tid);
            float2 p01 = pp2[0], p23 = pp2[1], p45 = pp2[2];
            const float* cc = s_c[slot] + 3 * tid;
            float c0 = cc[0], c1 = cc[1], c2 = cc[2];
            float4 y = *(const float4*)(s_y[slot] + 4 * tid);

            __syncwarp();
            if (lane == 0) mbar_arrive(eb0 + 8u * slot);

            // compute overlaps the producer's refill of this slot
            acc += row_loss(rr.x, rr.y,
                            p01.x, p01.y, p23.x, p23.y, p45.x, p45.y,
                            c0, c1, c2,
                            y.x, y.y, y.z, y.w);

            if (++slot == STAGES) { slot = 0; phase ^= 1; }
        }

        // tail rows (n % TILE): direct loads, block 0 consumers only
        if (blockIdx.x == 0) {
            for (int i = ntiles * TILE + tid; i < n; i += NCONS) {
                long li = i;
                float2 rr  = *(const float2*)(pred_r      + 2 * li);
                float2 p01 = *(const float2*)(pred_params + 6 * li);
                float2 p23 = *(const float2*)(pred_params + 6 * li + 2);
                float2 p45 = *(const float2*)(pred_params + 6 * li + 4);
                const float* pc = pred_corr + 3 * li;
                float4 y   = *(const float4*)(y_true + 4 * li);
                acc += row_loss(rr.x, rr.y,
                                p01.x, p01.y, p23.x, p23.y, p45.x, p45.y,
                                pc[0], pc[1], pc[2],
                                y.x, y.y, y.z, y.w);
            }
        }
    }

    // ---- intra-block reduce (9 warps; producer contributes 0) ----
    #pragma unroll
    for (int o = 16; o; o >>= 1)
        acc += __shfl_xor_sync(0xFFFFFFFFu, acc, o);

    __shared__ float warpsums[NTHREADS / 32];
    __shared__ bool  amLast;
    if (lane == 0) warpsums[wid] = acc;
    __syncthreads();

    if (tid == 0) {
        double bs = 0.0;
        #pragma unroll
        for (int w = 0; w < NTHREADS / 32; w++) bs += (double)warpsums[w];
        g_partials[blockIdx.x] = bs;
        __threadfence();
        unsigned int tk = atomicAdd(&g_counter, 1u);
        amLast = (tk == gridDim.x - 1);
    }
    __syncthreads();

    // ---- last block: deterministic final reduction ----
    if (amLast) {
        __shared__ double sh[NTHREADS];
        double s = 0.0;
        volatile double* gpp = g_partials;
        for (int k = tid; k < NBLOCKS; k += NTHREADS) s += gpp[k];
        sh[tid] = s;
        __syncthreads();
        // fold the 32 extra lanes (256..287) into 0..31, then tree over 256
        if (tid < NTHREADS - 256) sh[tid] += sh[256 + tid];
        __syncthreads();
        for (int st = 128; st > 0; st >>= 1) {
            if (tid < st) sh[tid] += sh[tid + st];
            __syncthreads();
        }
        if (tid == 0) {
            out[0] = (float)(sh[0] / (double)n);
            g_counter = 0;   // reset for next graph replay
        }
    }
}

extern "C" void kernel_launch(void* const* d_in, const int* in_sizes, int n_in,
                              void* d_out, int out_size)
{
    const float* pred_r      = (const float*)d_in[0];
    const float* pred_params = (const float*)d_in[1];
    const float* pred_corr   = (const float*)d_in[2];
    const float* y_true      = (const float*)d_in[3];
    int n = in_sizes[0] / 2;   // pred_r is (B, 2)

    gausscop_dual<<<NBLOCKS, NTHREADS>>>(pred_r, pred_params, pred_corr,
                                         y_true, (float*)d_out, n);
}

// round 16
// speedup vs baseline: 1.0587x; 1.0485x over previous
#include <cuda_runtime.h>
#include <cstdint>

#define NBLOCKS  304              // 152 SMs (GB300) x 2 blocks
#define NTHREADS 288              // 8 consumer warps + 1 producer warp
#define NCONS    256
#define CWARPS   8
#define PROD_W   8
#define TILE     256
#define STAGES   5
#define EPS      0.0001f

__device__ double       g_partials[NBLOCKS];
__device__ unsigned int g_counter = 0;

// z = clamp((x-u)/s, -3, 3): exact simplification of
// sqrt2*erfinv(2*clip(ndtr(t),eps,1-eps)-1) clipped to [-3,3]
// (Phi^-1(eps) = -3.719 < -3 so the eps clip never binds in [-3,3]).
// nll = 0.5*t^2 + param (s = exp(param)); 1/s = exp(-param); EPS floor
// binds only at param <= -9.21, far outside data range; z-clamp bounds it anyway.
__device__ __forceinline__ float row_loss(
    float ra, float rb,
    float pu1, float ps1, float pu2, float ps2, float pu3, float ps3,
    float r12, float r13, float r23,
    float revert, float Rtop, float Top, float Close)
{
    float u1 = __expf(pu1), rs1 = __expf(-ps1);
    float u2 = __expf(pu2), rs2 = __expf(-ps2);
    float u3 = __expf(pu3), rs3 = __expf(-ps3);

    float t1 = (Rtop  - u1) * rs1;
    float t2 = (Top   - u2) * rs2;
    float t3 = (Close - u3) * rs3;
    float z1 = fminf(fmaxf(t1, -3.0f), 3.0f);
    float z2 = fminf(fmaxf(t2, -3.0f), 3.0f);
    float z3 = fminf(fmaxf(t3, -3.0f), 3.0f);

    float nll_sum = 0.5f * (t1 * t1 + t2 * t2 + t3 * t3) + (ps1 + ps2 + ps3);

    float detR = 1.0f + 2.0f * r12 * r13 * r23
               - r12 * r12 - r13 * r13 - r23 * r23;
    float inv_det = 1.0f / detR;
    float i00 = (1.0f - r23 * r23) * inv_det;
    float i01 = (r13 * r23 - r12) * inv_det;
    float i02 = (r12 * r23 - r13) * inv_det;
    float i11 = (1.0f - r13 * r13) * inv_det;
    float i12 = (r12 * r13 - r23) * inv_det;
    float i22 = (1.0f - r12 * r12) * inv_det;

    float exp_term = 0.5f * ((i00 - 1.0f) * z1 * z1
                           + (i11 - 1.0f) * z2 * z2
                           + (i22 - 1.0f) * z3 * z3)
                   + (i01 * z1 * z2 + i02 * z1 * z3 + i12 * z2 * z3);

    float c_gauss = 0.5f * __logf(fmaxf(detR, EPS)) + exp_term;
    float copula  = revert * (c_gauss + nll_sum);

    float m   = fmaxf(ra, rb);
    float lse = m + __logf(1.0f + __expf(-fabsf(ra - rb)));
    float sel = (revert != 0.0f) ? rb : ra;
    return (lse - sel) + copula;
}

__device__ __forceinline__ uint32_t smem_u32(const void* p) {
    return (uint32_t)__cvta_generic_to_shared(p);
}
__device__ __forceinline__ void mbar_init(uint32_t mbar, uint32_t cnt) {
    asm volatile("mbarrier.init.shared.b64 [%0], %1;" :: "r"(mbar), "r"(cnt) : "memory");
}
__device__ __forceinline__ void mbar_expect_tx(uint32_t mbar, uint32_t bytes) {
    asm volatile("mbarrier.arrive.expect_tx.shared.b64 _, [%0], %1;"
                 :: "r"(mbar), "r"(bytes) : "memory");
}
__device__ __forceinline__ void mbar_arrive(uint32_t mbar) {
    asm volatile("mbarrier.arrive.shared.b64 _, [%0];" :: "r"(mbar) : "memory");
}
__device__ __forceinline__ void bulk_g2s(uint32_t dst, const void* src,
                                         uint32_t bytes, uint32_t mbar) {
    asm volatile(
        "cp.async.bulk.shared::cta.global.mbarrier::complete_tx::bytes "
        "[%0], [%1], %2, [%3];"
        :: "r"(dst), "l"(src), "r"(bytes), "r"(mbar) : "memory");
}
__device__ __forceinline__ void mbar_wait(uint32_t mbar, uint32_t parity) {
    uint32_t done;
    asm volatile(
        "{\n\t.reg .pred p;\n\t"
        "mbarrier.try_wait.parity.acquire.cta.shared::cta.b64 p, [%1], %2;\n\t"
        "selp.b32 %0, 1, 0, p;\n\t}"
        : "=r"(done) : "r"(mbar), "r"(parity) : "memory");
    if (!done) {
        asm volatile(
            "{\n\t.reg .pred P1;\n\t"
            "WL_%=:\n\t"
            "mbarrier.try_wait.parity.acquire.cta.shared::cta.b64 P1, [%0], %1, 0x989680;\n\t"
            "@P1 bra.uni WD_%=;\n\t"
            "bra.uni WL_%=;\n\t"
            "WD_%=:\n\t}"
            :: "r"(mbar), "r"(parity) : "memory");
    }
}

__global__ __launch_bounds__(NTHREADS, 2)
void gausscop_ws(const float* __restrict__ pred_r,
                 const float* __restrict__ pred_params,
                 const float* __restrict__ pred_corr,
                 const float* __restrict__ y_true,
                 float* __restrict__ out,
                 int n)
{
    __shared__ alignas(128) float s_r[STAGES][TILE * 2];
    __shared__ alignas(128) float s_p[STAGES][TILE * 6];
    __shared__ alignas(128) float s_c[STAGES][TILE * 3];
    __shared__ alignas(128) float s_y[STAGES][TILE * 4];
    __shared__ alignas(8)  uint64_t full_bar[STAGES];
    __shared__ alignas(8)  uint64_t empty_bar[STAGES];

    const int tid  = threadIdx.x;
    const int lane = tid & 31;
    const int wid  = tid >> 5;
    const uint32_t fb0 = smem_u32(&full_bar[0]);
    const uint32_t eb0 = smem_u32(&empty_bar[0]);

    if (tid == 0) {
        #pragma unroll
        for (int s = 0; s < STAGES; s++) {
            mbar_init(fb0 + 8u * s, 1);        // tx-based (producer expect_tx)
            mbar_init(eb0 + 8u * s, CWARPS);   // one arrive per consumer warp
        }
    }
    __syncthreads();

    const int ntiles = n / TILE;
    int nlocal = 0;
    if ((int)blockIdx.x < ntiles)
        nlocal = (ntiles - blockIdx.x + NBLOCKS - 1) / NBLOCKS;

    const uint32_t TILE_BYTES = TILE * 60u;

    float acc = 0.0f;

    if (wid == PROD_W) {
        // ======= producer warp: TMA issue only =======
        int slot = 0, phase = 1;   // flipped phase: first STAGES empty-waits pass
        for (int j = 0; j < nlocal; j++) {
            mbar_wait(eb0 + 8u * slot, (uint32_t)phase);
            if (lane == 0) {
                long base = ((long)blockIdx.x + (long)j * NBLOCKS) * TILE;
                uint32_t mb = fb0 + 8u * slot;
                mbar_expect_tx(mb, TILE_BYTES);
                bulk_g2s(smem_u32(s_r[slot]), pred_r      + 2 * base, TILE * 8,  mb);
                bulk_g2s(smem_u32(s_p[slot]), pred_params + 6 * base, TILE * 24, mb);
                bulk_g2s(smem_u32(s_c[slot]), pred_corr   + 3 * base, TILE * 12, mb);
                bulk_g2s(smem_u32(s_y[slot]), y_true      + 4 * base, TILE * 16, mb);
            }
            if (++slot == STAGES) { slot = 0; phase ^= 1; }
        }
    } else {
        // ======= consumer warps =======
        int slot = 0, phase = 0;
        for (int j = 0; j < nlocal; j++) {
            mbar_wait(fb0 + 8u * slot, (uint32_t)phase);

            // drain this thread's row into registers (short slot dwell)
            float2 rr = *(const float2*)(s_r[slot] + 2 * tid);
            const float2* pp2 = (const float2*)(s_p[slot] + 6 * tid);
            float2 p01 = pp2[0], p23 = pp2[1], p45 = pp2[2];
            const float* cc = s_c[slot] + 3 * tid;
            float c0 = cc[0], c1 = cc[1], c2 = cc[2];
            float4 y = *(const float4*)(s_y[slot] + 4 * tid);

            __syncwarp();
            if (lane == 0) mbar_arrive(eb0 + 8u * slot);

            // compute overlaps the producer's refill of this slot
            acc += row_loss(rr.x, rr.y,
                            p01.x, p01.y, p23.x, p23.y, p45.x, p45.y,
                            c0, c1, c2,
                            y.x, y.y, y.z, y.w);

            if (++slot == STAGES) { slot = 0; phase ^= 1; }
        }

        // tail rows (n % TILE): direct loads, block 0 consumers only
        if (blockIdx.x == 0) {
            for (int i = ntiles * TILE + tid; i < n; i += NCONS) {
                long li = i;
                float2 rr  = *(const float2*)(pred_r      + 2 * li);
                float2 p01 = *(const float2*)(pred_params + 6 * li);
                float2 p23 = *(const float2*)(pred_params + 6 * li + 2);
                float2 p45 = *(const float2*)(pred_params + 6 * li + 4);
                const float* pc = pred_corr + 3 * li;
                float4 y   = *(const float4*)(y_true + 4 * li);
                acc += row_loss(rr.x, rr.y,
                                p01.x, p01.y, p23.x, p23.y, p45.x, p45.y,
                                pc[0], pc[1], pc[2],
                                y.x, y.y, y.z, y.w);
            }
        }
    }

    // ---- intra-block reduce (9 warps; producer contributes 0) ----
    #pragma unroll
    for (int o = 16; o; o >>= 1)
        acc += __shfl_xor_sync(0xFFFFFFFFu, acc, o);

    __shared__ float warpsums[NTHREADS / 32];
    __shared__ bool  amLast;
    if (lane == 0) warpsums[wid] = acc;
    __syncthreads();

    if (tid == 0) {
        double bs = 0.0;
        #pragma unroll
        for (int w = 0; w < NTHREADS / 32; w++) bs += (double)warpsums[w];
        g_partials[blockIdx.x] = bs;
        __threadfence();
        unsigned int tk = atomicAdd(&g_counter, 1u);
        amLast = (tk == gridDim.x - 1);
    }
    __syncthreads();

    // ---- last block: deterministic final reduction ----
    if (amLast) {
        __shared__ double sh[NTHREADS];
        double s = 0.0;
        volatile double* gpp = g_partials;
        for (int k = tid; k < NBLOCKS; k += NTHREADS) s += gpp[k];
        sh[tid] = s;
        __syncthreads();
        // fold the 32 extra lanes (256..287) into 0..31, then tree over 256
        if (tid < NTHREADS - 256) sh[tid] += sh[256 + tid];
        __syncthreads();
        for (int st = 128; st > 0; st >>= 1) {
            if (tid < st) sh[tid] += sh[tid + st];
            __syncthreads();
        }
        if (tid == 0) {
            out[0] = (float)(sh[0] / (double)n);
            g_counter = 0;   // reset for next graph replay
        }
    }
}

extern "C" void kernel_launch(void* const* d_in, const int* in_sizes, int n_in,
                              void* d_out, int out_size)
{
    const float* pred_r      = (const float*)d_in[0];
    const float* pred_params = (const float*)d_in[1];
    const float* pred_corr   = (const float*)d_in[2];
    const float* y_true      = (const float*)d_in[3];
    int n = in_sizes[0] / 2;   // pred_r is (B, 2)

    gausscop_ws<<<NBLOCKS, NTHREADS>>>(pred_r, pred_params, pred_corr,
                                       y_true, (float*)d_out, n);
}